// round 9
// baseline (speedup 1.0000x reference)
#include <cuda_runtime.h>

#define BATCH 32
#define HW    16384          // 128*128
#define NPIX  (BATCH * HW)   // 524288
#define NMIXK 10
#define TPB   256
#define NBLK  (NPIX / TPB)   // 2048

__device__ double       g_part[NBLK];
__device__ unsigned int g_count = 0;

// hardware tanh: 1 MUFU op, abs err ~5e-4
__device__ __forceinline__ float tanh_hw(float v) {
    float r;
    asm("tanh.approx.f32 %0, %1;" : "=f"(r) : "f"(v));
    return r;
}

// FAST per-(channel, mixture) log-prob: 3 MUFU, NO |x|>0.999 handling.
// Valid only when |x| <= 0.999 (edge pixels take slow_pixel below).
//
// log(cdf_delta) = log(2d) + log(sinh(d)/d) - |mid| - log(denom),
//   g = exp(-|mid|), denom = 1 + 2 g cosh(d) + g^2,
//   log(2d) = log(2/255) - ls  (exact).
// Reference's small-delta fallback = same expression minus log(sinh d / d),
// so the 1e-5 branch is a predicated add of a 2-FMA polynomial.
__device__ __forceinline__ float chlp_fast(float x, float mu, float lsr) {
    float ls  = fmaxf(lsr, -7.0f);
    float inv = __expf(-ls);                             // MUFU 1
    float mid = inv * (x - mu);
    float d   = inv * (1.0f / 255.0f);                   // half-width > 0
    float am  = fabsf(mid);
    float g   = __expf(-am);                             // MUFU 2

    float d2 = d * d;
    // polynomials valid for d <= 1 (typical d ~ 4e-3)
    float sh     = d * fmaf(d2, fmaf(d2, 8.3333333e-3f, 0.16666667f), 1.0f);
    float ch     = fmaf(d2, fmaf(d2, 4.1666667e-2f, 0.5f), 1.0f);
    float log_sc = d2 * fmaf(d2, -5.5555556e-3f, 0.16666667f);

    if (d > 1.0f) {                                      // ultra-rare exact path
        float ed = __expf(d), edi = __expf(-d);
        sh     = 0.5f * (ed - edi);
        ch     = 0.5f * (ed + edi);
        log_sc = __logf(sh * __fdividef(1.0f, d));
    }

    float denom = fmaf(2.0f * ch, g, fmaf(g, g, 1.0f));
    float corr  = (2.0f * g * sh > 1e-5f * denom) ? log_sc : 0.0f;
    return -ls - 4.8481164f - am - __logf(denom) + corr; // MUFU 3
}

// FULL per-(channel, mixture) log-prob including |x|>0.999 edges (cold path).
__device__ float chlp_full(float x, float mu, float lsr) {
    float inner = chlp_fast(x, mu, lsr);
    float ls  = fmaxf(lsr, -7.0f);
    float inv = __expf(-ls);
    float mid = inv * (x - mu);
    float d   = inv * (1.0f / 255.0f);
    if (x < -0.999f) {
        float pz = mid + d;
        inner = fminf(pz, 0.0f) - __logf(1.0f + __expf(-fabsf(pz)));
    } else if (x > 0.999f) {
        float q = mid - d;
        inner = -fmaxf(q, 0.0f) - __logf(1.0f + __expf(-fabsf(q)));
    }
    return inner;
}

// Cold full-pixel recompute for edge pixels (~0.3% of pixels).
__device__ __noinline__ float slow_pixel(const float* __restrict__ pp,
                                         float x0, float x1, float x2) {
    float se = 0.0f;
    float lp[NMIXK];
    #pragma unroll 1
    for (int m = 0; m < NMIXK; m++) {
        float lg  = __ldg(pp + (     m) * HW);
        float mu1 = __ldg(pp + (10 + m) * HW);
        float ls1 = __ldg(pp + (20 + m) * HW);
        float c0r = __ldg(pp + (30 + m) * HW);
        float mu2 = __ldg(pp + (40 + m) * HW);
        float ls2 = __ldg(pp + (50 + m) * HW);
        float c1r = __ldg(pp + (60 + m) * HW);
        float mu3 = __ldg(pp + (70 + m) * HW);
        float ls3 = __ldg(pp + (80 + m) * HW);
        float c2r = __ldg(pp + (90 + m) * HW);

        se += __expf(lg);
        float c0 = tanh_hw(c0r);
        float c1 = tanh_hw(c1r);
        float c2 = tanh_hw(c2r);
        float m2 = fmaf(c0, x0, mu2);
        float m3 = fmaf(c2, x1, fmaf(c1, x0, mu3));

        lp[m] = lg + chlp_full(x0, mu1, ls1)
                   + chlp_full(x1, m2,  ls2)
                   + chlp_full(x2, m3,  ls3);
    }
    float mx = lp[0];
    #pragma unroll
    for (int i = 1; i < NMIXK; i++) mx = fmaxf(mx, lp[i]);
    float s = 0.0f;
    #pragma unroll
    for (int i = 0; i < NMIXK; i++) s += __expf(lp[i] - mx);
    return mx + __logf(s) - __logf(se);
}

__global__ void __launch_bounds__(TPB, 8) pixlp_kernel(
    const float* __restrict__ samples, const float* __restrict__ params,
    float* __restrict__ out)
{
    int p  = blockIdx.x * TPB + threadIdx.x;
    int b  = p >> 14;
    int hw = p & (HW - 1);
    const float* sp = samples + (size_t)b * 3   * HW + hw;
    const float* pp = params  + (size_t)b * 100 * HW + hw;

    float x0 = fmaf(2.0f, __ldg(sp),          -1.0f);
    float x1 = fmaf(2.0f, __ldg(sp + HW),     -1.0f);
    float x2 = fmaf(2.0f, __ldg(sp + 2 * HW), -1.0f);

    float se = 0.0f;                 // sum exp(logits), overflow-safe (|logits| small)
    float mx = -1e30f, s = 0.0f;     // online LSE over mixtures (1 exp per update)

    #pragma unroll
    for (int m = 0; m < NMIXK; m++) {
        float lg  = __ldg(pp + (     m) * HW);
        float mu1 = __ldg(pp + (10 + m) * HW);
        float ls1 = __ldg(pp + (20 + m) * HW);
        float c0r = __ldg(pp + (30 + m) * HW);
        float mu2 = __ldg(pp + (40 + m) * HW);
        float ls2 = __ldg(pp + (50 + m) * HW);
        float c1r = __ldg(pp + (60 + m) * HW);
        float mu3 = __ldg(pp + (70 + m) * HW);
        float ls3 = __ldg(pp + (80 + m) * HW);
        float c2r = __ldg(pp + (90 + m) * HW);

        se += __expf(lg);

        float c0 = tanh_hw(c0r);
        float c1 = tanh_hw(c1r);
        float c2 = tanh_hw(c2r);
        float m2 = fmaf(c0, x0, mu2);
        float m3 = fmaf(c2, x1, fmaf(c1, x0, mu3));

        float lpm = lg + chlp_fast(x0, mu1, ls1)
                       + chlp_fast(x1, m2,  ls2)
                       + chlp_fast(x2, m3,  ls3);

        // one-exp online logsumexp
        float dd = lpm - mx;
        float e  = __expf(-fabsf(dd));
        if (dd <= 0.0f) { s += e; }
        else            { s = fmaf(s, e, 1.0f); mx = lpm; }
    }

    float val = mx + __logf(s) - __logf(se);

    // rare edge pixels (any |x| > 0.999): full recompute on cold path
    float ax = fmaxf(fabsf(x0), fmaxf(fabsf(x1), fabsf(x2)));
    if (ax > 0.999f) val = slow_pixel(pp, x0, x1, x2);

    // block reduction (fp32 within block)
    __shared__ float red[TPB];
    int t = threadIdx.x;
    red[t] = val;
    __syncthreads();
    #pragma unroll
    for (int off = TPB / 2; off > 32; off >>= 1) {
        if (t < off) red[t] += red[t + off];
        __syncthreads();
    }
    if (t < 32) {
        float w = red[t] + red[t + 32];
        #pragma unroll
        for (int off = 16; off > 0; off >>= 1)
            w += __shfl_down_sync(0xFFFFFFFFu, w, off);
        if (t == 0) red[0] = w;
    }
    __syncthreads();

    // block partial (double), last block finishes — no helper kernels
    __shared__ bool amLast;
    if (t == 0) {
        g_part[blockIdx.x] = (double)red[0];
        __threadfence();
        unsigned int done = atomicAdd(&g_count, 1u);
        amLast = (done == NBLK - 1);
    }
    __syncthreads();

    if (amLast) {
        __shared__ double redd[TPB];
        double sd = 0.0;
        for (int i = t; i < NBLK; i += TPB) sd += g_part[i];
        redd[t] = sd;
        __syncthreads();
        #pragma unroll
        for (int off = TPB / 2; off > 0; off >>= 1) {
            if (t < off) redd[t] += redd[t + off];
            __syncthreads();
        }
        if (t == 0) {
            out[0] = (float)redd[0];
            g_count = 0;                      // reset for next graph replay
        }
    }
}

extern "C" void kernel_launch(void* const* d_in, const int* in_sizes, int n_in,
                              void* d_out, int out_size)
{
    const float* samples;
    const float* params;
    if (in_sizes[0] == BATCH * 3 * HW) {
        samples = (const float*)d_in[0];
        params  = (const float*)d_in[1];
    } else {
        samples = (const float*)d_in[1];
        params  = (const float*)d_in[0];
    }
    pixlp_kernel<<<NBLK, TPB>>>(samples, params, (float*)d_out);
}